// round 16
// baseline (speedup 1.0000x reference)
#include <cuda_runtime.h>

#define BB 256
#define NN 512
#define INF 10
#define HIDF 32
#define R 128                     // rows per block
#define WARPS 8
#define THREADS (WARPS * 32)
#define CHUNKS (NN / R)           // 4
#define TP 520                    // transposed s row stride (pad)

typedef unsigned long long u64;

// ---- packed f32x2 helpers (sm_103a FFMA2 path, PTX-only) -------------------
__device__ __forceinline__ u64 pk2(float lo, float hi) {
    u64 r; asm("mov.b64 %0,{%1,%2};" : "=l"(r) : "f"(lo), "f"(hi)); return r;
}
__device__ __forceinline__ void upk2(u64 v, float& lo, float& hi) {
    asm("mov.b64 {%0,%1},%2;" : "=f"(lo), "=f"(hi) : "l"(v));
}
__device__ __forceinline__ u64 fma2(u64 a, u64 b, u64 c) {
    u64 r; asm("fma.rn.f32x2 %0,%1,%2,%3;" : "=l"(r) : "l"(a), "l"(b), "l"(c)); return r;
}
__device__ __forceinline__ u64 mul2f(u64 a, u64 b) {
    u64 r; asm("mul.rn.f32x2 %0,%1,%2;" : "=l"(r) : "l"(a), "l"(b)); return r;
}
__device__ __forceinline__ u64 add2f(u64 a, u64 b) {
    u64 r; asm("add.rn.f32x2 %0,%1,%2;" : "=l"(r) : "l"(a), "l"(b)); return r;
}

// ---------------------------------------------------------------------------
// R15's loop with half-column warps for occupancy 3.
// Block = (batch b, 128-row quarter). Warp w: pair group pg = w>>1 handles
// pairs p = pg + 4k (k<16); column half = w&1 covers 256 columns.
// acc[8] (16 regs) + tp[10] (20 regs) -> ~75 regs -> 3 blocks/SM.
// The two half-warps of a pair exchange packed row sums via a double-
// buffered smem slot + one __syncthreads per k.
// ---------------------------------------------------------------------------
__global__ __launch_bounds__(THREADS, 3) void attn_main(
    const float* __restrict__ s,
    const float* __restrict__ Gmat,
    const float* __restrict__ Qw,
    const float* __restrict__ Kw,
    float* __restrict__ out) {
    __shared__ float s_smT[INF * TP];    // s[b] transposed (20.8 KB)
    __shared__ float Msh[INF * INF];
    __shared__ float t_sm[R][INF];       // t for the block's 128 rows
    __shared__ u64 psum2[2][4][2];       // [parity][pair group][half]

    const int tid = threadIdx.x;
    const int b = blockIdx.x / CHUNKS;
    const int row0 = (blockIdx.x % CHUNKS) * R;

    // ---- Stage 1: s[b] -> smem transposed; M in-block
    {
        const float* sb = s + (size_t)b * NN * INF;
        for (int n = tid; n < NN; n += THREADS) {
#pragma unroll
            for (int i = 0; i < INF; i++)
                s_smT[i * TP + n] = sb[n * INF + i];
        }
    }
    if (tid < INF * INF) {
        const int a = tid / INF, p = tid % INF;
        float acc = 0.0f;
#pragma unroll
        for (int m = 0; m < HIDF; m++)
            acc = fmaf(Qw[a * HIDF + m], Kw[p * HIDF + m], acc);
        Msh[tid] = acc;
    }
    __syncthreads();

    // ---- Stage 2: t for 128 rows, all 256 threads (5 values each)
#pragma unroll
    for (int kk = 0; kk < (R * INF) / THREADS; kk++) {
        const int idx = tid + kk * THREADS;
        const int r = idx / INF, o = idx % INF;
        const int n = row0 + r;
        float acc = 0.0f;
#pragma unroll
        for (int l = 0; l < INF; l++)
            acc = fmaf(s_smT[l * TP + n], Msh[l * INF + o], acc);
        t_sm[r][o] = acc;
    }
    __syncthreads();

    // ---- warp decomposition: pair group + column half
    const int w = tid >> 5, lane = tid & 31;
    const int pg = w >> 1;               // 0..3
    const int half = w & 1;              // 0..1
    const int jbase = (half << 8) + lane;

    for (int k = 0; k < 16; k++) {
        const int p = pg + (k << 2);     // pair index 0..63
        const int r0 = 2 * p;
        const int n0 = row0 + r0;

        u64 tp[INF];
#pragma unroll
        for (int i = 0; i < INF; i++)
            tp[i] = pk2(t_sm[r0][i], t_sm[r0 + 1][i]);

        const float* g0 = Gmat + ((size_t)b * NN + n0) * NN + jbase;
        const float* g1 = g0 + NN;

        u64 acc[8];
        u64 sum2 = pk2(0.0f, 0.0f);
#pragma unroll
        for (int u = 0; u < 8; u++) {
            const int j = jbase + (u << 5);
            u64 d = pk2(0.0f, 0.0f);
#pragma unroll
            for (int i = 0; i < INF; i++) {
                const float sj = s_smT[i * TP + j];   // conflict-free LDS
                d = fma2(tp[i], pk2(sj, sj), d);
            }
            const int uo = u << 5;
            const u64 g = pk2(g0[uo], g1[uo]);
            const u64 v = mul2f(mul2f(d, d), g);
            acc[u] = v;
            sum2 = add2f(sum2, v);
        }

        // packed warp reduction of both row half-sums
#pragma unroll
        for (int off = 16; off > 0; off >>= 1)
            sum2 = add2f(sum2, __shfl_xor_sync(0xffffffffu, sum2, off));

        // exchange with sibling half-warp (double-buffered slot, parity k&1)
        if (lane == 0) psum2[k & 1][pg][half] = sum2;
        __syncthreads();
        const u64 tot = add2f(sum2, psum2[k & 1][pg][half ^ 1]);

        float sa, sb2;
        upk2(tot, sa, sb2);
        const float inv0 = 1.0f / (sa + 0.001f);
        const float inv1 = 1.0f / (sb2 + 0.001f);

        float* o0 = out + ((size_t)b * NN + n0) * NN + jbase;
        float* o1 = o0 + NN;
#pragma unroll
        for (int u = 0; u < 8; u++) {
            const int uo = u << 5;
            float a, bv;
            upk2(acc[u], a, bv);
            o0[uo] = a * inv0;
            o1[uo] = bv * inv1;
        }
    }
}

// ---------------------------------------------------------------------------
extern "C" void kernel_launch(void* const* d_in, const int* in_sizes, int n_in,
                              void* d_out, int out_size) {
    const float* s    = (const float*)d_in[0];
    const float* Gmat = (const float*)d_in[1];
    const float* Qw   = (const float*)d_in[2];
    const float* Kw   = (const float*)d_in[3];
    float* out = (float*)d_out;

    attn_main<<<BB * CHUNKS, THREADS>>>(s, Gmat, Qw, Kw, out);
}

// round 17
// speedup vs baseline: 1.2365x; 1.2365x over previous
#include <cuda_runtime.h>

#define BB 256
#define NN 512
#define INF 10
#define HIDF 32
#define R 128                     // rows per block
#define WARPS 8
#define THREADS (WARPS * 32)
#define CHUNKS (NN / R)           // 4
#define TP 520                    // transposed s row stride (pad)

typedef unsigned long long u64;

// ---- packed f32x2 helpers (sm_103a FFMA2 path, PTX-only) -------------------
__device__ __forceinline__ u64 pk2(float lo, float hi) {
    u64 r; asm("mov.b64 %0,{%1,%2};" : "=l"(r) : "f"(lo), "f"(hi)); return r;
}
__device__ __forceinline__ void upk2(u64 v, float& lo, float& hi) {
    asm("mov.b64 {%0,%1},%2;" : "=f"(lo), "=f"(hi) : "l"(v));
}
__device__ __forceinline__ u64 fma2(u64 a, u64 b, u64 c) {
    u64 r; asm("fma.rn.f32x2 %0,%1,%2,%3;" : "=l"(r) : "l"(a), "l"(b), "l"(c)); return r;
}
__device__ __forceinline__ u64 mul2f(u64 a, u64 b) {
    u64 r; asm("mul.rn.f32x2 %0,%1,%2;" : "=l"(r) : "l"(a), "l"(b)); return r;
}
__device__ __forceinline__ u64 add2f(u64 a, u64 b) {
    u64 r; asm("add.rn.f32x2 %0,%1,%2;" : "=l"(r) : "l"(a), "l"(b)); return r;
}

// ---------------------------------------------------------------------------
// R15 macro-structure (128-row blocks, warp sweeps 8 row-pairs over all 512
// columns) with j-PACKED s operands:
//   lane owns column pair {2*lane + 64u}; s read as LDS.64 -> ready f32x2;
//   t splats hoisted out of the u-loop (pair-invariant);
//   inner loop: 10 LDS.64 + 20 fma2 per 128 elems, zero MOVs;
//   G via LDG.64, out via STG.64; acc in registers, single-pass normalize.
// ---------------------------------------------------------------------------
__global__ __launch_bounds__(THREADS, 2) void attn_main(
    const float* __restrict__ s,
    const float* __restrict__ Gmat,
    const float* __restrict__ Qw,
    const float* __restrict__ Kw,
    float* __restrict__ out) {
    __shared__ float s_smT[INF * TP];    // s[b] transposed (20.8 KB)
    __shared__ float Msh[INF * INF];
    __shared__ float t_sm[R][INF];       // t for the block's 128 rows

    const int tid = threadIdx.x;
    const int b = blockIdx.x / CHUNKS;
    const int row0 = (blockIdx.x % CHUNKS) * R;

    // ---- Stage 1: s[b] -> smem transposed; M in-block
    {
        const float* sb = s + (size_t)b * NN * INF;
        for (int n = tid; n < NN; n += THREADS) {
#pragma unroll
            for (int i = 0; i < INF; i++)
                s_smT[i * TP + n] = sb[n * INF + i];
        }
    }
    if (tid < INF * INF) {
        const int a = tid / INF, p = tid % INF;
        float acc = 0.0f;
#pragma unroll
        for (int m = 0; m < HIDF; m++)
            acc = fmaf(Qw[a * HIDF + m], Kw[p * HIDF + m], acc);
        Msh[tid] = acc;
    }
    __syncthreads();

    // ---- Stage 2: t for 128 rows, all 256 threads (5 values each)
#pragma unroll
    for (int kk = 0; kk < (R * INF) / THREADS; kk++) {
        const int idx = tid + kk * THREADS;
        const int r = idx / INF, o = idx % INF;
        const int n = row0 + r;
        float acc = 0.0f;
#pragma unroll
        for (int l = 0; l < INF; l++)
            acc = fmaf(s_smT[l * TP + n], Msh[l * INF + o], acc);
        t_sm[r][o] = acc;
    }
    __syncthreads();

    // ---- Stage 3: main loop, j-packed operands
    const int w = tid >> 5, lane = tid & 31;
    const int j0 = lane << 1;            // lane's base column pair

    for (int k = 0; k < 8; k++) {        // 8 row-pairs per warp (not unrolled)
        const int p = w + (k << 3);      // pair index 0..63
        const int r0 = 2 * p;
        const int n0 = row0 + r0;

        // hoisted t splats (pair-invariant, 40 regs)
        u64 tp0[INF], tp1[INF];
#pragma unroll
        for (int i = 0; i < INF; i++) {
            const float t0 = t_sm[r0][i];
            const float t1 = t_sm[r0 + 1][i];
            tp0[i] = pk2(t0, t0);
            tp1[i] = pk2(t1, t1);
        }

        const char* g0 = (const char*)(Gmat + ((size_t)b * NN + n0) * NN + j0);
        const char* g1 = g0 + NN * 4;

        u64 acc0[8], acc1[8];
        u64 sum0 = pk2(0.0f, 0.0f);
        u64 sum1 = pk2(0.0f, 0.0f);

#pragma unroll
        for (int u = 0; u < 8; u++) {
            const int off = u << 6;      // 64-column stride
            u64 d0 = pk2(0.0f, 0.0f);
            u64 d1 = pk2(0.0f, 0.0f);
#pragma unroll
            for (int i = 0; i < INF; i++) {
                const u64 s2 = *(const u64*)(s_smT + i * TP + j0 + off);  // LDS.64
                d0 = fma2(s2, tp0[i], d0);
                d1 = fma2(s2, tp1[i], d1);
            }
            const u64 gA = *(const u64*)(g0 + (size_t)off * 4);   // LDG.64
            const u64 gB = *(const u64*)(g1 + (size_t)off * 4);
            const u64 v0 = mul2f(mul2f(d0, d0), gA);
            const u64 v1 = mul2f(mul2f(d1, d1), gB);
            acc0[u] = v0;
            acc1[u] = v1;
            sum0 = add2f(sum0, v0);
            sum1 = add2f(sum1, v1);
        }

        // horizontal pair-sum, then packed 5-shuffle row reduction
        float x0, y0, x1, y1;
        upk2(sum0, x0, y0);
        upk2(sum1, x1, y1);
        u64 sr = pk2(x0 + y0, x1 + y1);
#pragma unroll
        for (int off = 16; off > 0; off >>= 1)
            sr = add2f(sr, __shfl_xor_sync(0xffffffffu, sr, off));

        float sa, sb2;
        upk2(sr, sa, sb2);
        const float inv0 = 1.0f / (sa + 0.001f);
        const float inv1 = 1.0f / (sb2 + 0.001f);
        const u64 iv0 = pk2(inv0, inv0);
        const u64 iv1 = pk2(inv1, inv1);

        char* o0 = (char*)(out + ((size_t)b * NN + n0) * NN + j0);
        char* o1 = o0 + NN * 4;
#pragma unroll
        for (int u = 0; u < 8; u++) {
            const int off = u << 6;
            *(u64*)(o0 + (size_t)off * 4) = mul2f(acc0[u], iv0);  // STG.64
            *(u64*)(o1 + (size_t)off * 4) = mul2f(acc1[u], iv1);
        }
    }
}

// ---------------------------------------------------------------------------
extern "C" void kernel_launch(void* const* d_in, const int* in_sizes, int n_in,
                              void* d_out, int out_size) {
    const float* s    = (const float*)d_in[0];
    const float* Gmat = (const float*)d_in[1];
    const float* Qw   = (const float*)d_in[2];
    const float* Kw   = (const float*)d_in[3];
    float* out = (float*)d_out;

    attn_main<<<BB * CHUNKS, THREADS>>>(s, Gmat, Qw, Kw, out);
}